// round 1
// baseline (speedup 1.0000x reference)
#include <cuda_runtime.h>

#define NB   128
#define NBP  129          // padded row stride: bank = (i + j) % 32, mixes both indices
#define RAD  5
#define W    (2*RAD+1)    // 11

__device__ float g_hist[NB * NB];

__global__ void zero_hist_kernel() {
    int i = blockIdx.x * blockDim.x + threadIdx.x;
    if (i < NB * NB) g_hist[i] = 0.0f;
}

__global__ void accum_kernel(const float* __restrict__ x,
                             const float* __restrict__ ex,
                             const float* __restrict__ ey,
                             int n) {
    extern __shared__ float sh[];   // NB * NBP floats
    for (int i = threadIdx.x; i < NB * NBP; i += blockDim.x) sh[i] = 0.0f;
    __syncthreads();

    // bin geometry from edges (linspace): width + first center
    const float bwx = ex[1] - ex[0];
    const float bwy = ey[1] - ey[0];
    const float inv_bwx = 1.0f / bwx;
    const float inv_bwy = 1.0f / bwy;
    const float c0x = 0.5f * (ex[0] + ex[1]);
    const float c0y = 0.5f * (ey[0] + ey[1]);
    const float EINV = 0.36787944117144233f;   // e^-1

    const int stride = gridDim.x * blockDim.x;
    for (int p = blockIdx.x * blockDim.x + threadIdx.x; p < n; p += stride) {
        float px = __ldg(&x[p * 6 + 0]);
        float py = __ldg(&x[p * 6 + 1]);
        float ux = (px - c0x) * inv_bwx;       // position in bin-center units
        float uy = (py - c0y) * inv_bwy;
        int ix0 = __float2int_rn(ux);
        int iy0 = __float2int_rn(uy);
        int ilo = max(0, ix0 - RAD), ihi = min(NB - 1, ix0 + RAD);
        int jlo = max(0, iy0 - RAD), jhi = min(NB - 1, iy0 + RAD);
        if (ilo > ihi || jlo > jhi) continue;
        int my = jhi - jlo + 1;

        // y-axis kernel values via multiplicative recurrence:
        // g(z-1) = g(z) * exp(z - 0.5); ratio decays by e^-1 per step.
        float kv[W];
        {
            float z = uy - (float)jlo;
            float g = __expf(-0.5f * z * z);
            float r = __expf(z - 0.5f);
            #pragma unroll
            for (int jj = 0; jj < W; ++jj) {
                kv[jj] = g;
                g *= r;
                r *= EINV;
            }
        }
        // x-axis recurrence + 2D scatter
        {
            float z = ux - (float)ilo;
            float g = __expf(-0.5f * z * z);
            float r = __expf(z - 0.5f);
            for (int i = ilo; i <= ihi; ++i) {
                float* row = &sh[i * NBP + jlo];
                #pragma unroll
                for (int jj = 0; jj < W; ++jj) {
                    if (jj < my) atomicAdd(&row[jj], g * kv[jj]);
                }
                g *= r;
                r *= EINV;
            }
        }
    }

    __syncthreads();
    // flush block-private hist to global
    for (int i = threadIdx.x; i < NB * NB; i += blockDim.x) {
        float v = sh[(i >> 7) * NBP + (i & (NB - 1))];
        if (v != 0.0f) atomicAdd(&g_hist[i], v);
    }
}

__global__ void normalize_kernel(float* __restrict__ out,
                                 const float* __restrict__ ex,
                                 const float* __restrict__ ey) {
    __shared__ float red[256];
    float s = 0.0f;
    for (int i = threadIdx.x; i < NB * NB; i += 256) s += g_hist[i];
    red[threadIdx.x] = s;
    __syncthreads();
    for (int off = 128; off > 0; off >>= 1) {
        if (threadIdx.x < off) red[threadIdx.x] += red[threadIdx.x + off];
        __syncthreads();
    }
    float bwx = ex[1] - ex[0];
    float bwy = ey[1] - ey[0];
    float scale = 1.0f / (red[0] * bwx * bwy);
    for (int i = threadIdx.x; i < NB * NB; i += 256) out[i] = g_hist[i] * scale;
}

extern "C" void kernel_launch(void* const* d_in, const int* in_sizes, int n_in,
                              void* d_out, int out_size) {
    const float* x  = (const float*)d_in[0];
    const float* ex = (const float*)d_in[1];
    const float* ey = (const float*)d_in[2];
    int n = in_sizes[0] / 6;

    const int SMEM = NB * NBP * (int)sizeof(float);   // 66048 B
    cudaFuncSetAttribute(accum_kernel, cudaFuncAttributeMaxDynamicSharedMemorySize, SMEM);

    zero_hist_kernel<<<(NB * NB + 255) / 256, 256>>>();
    // 3 CTAs/SM * 148 SMs = 444 persistent blocks
    accum_kernel<<<444, 256, SMEM>>>(x, ex, ey, n);
    normalize_kernel<<<1, 256>>>((float*)d_out, ex, ey);
}

// round 2
// speedup vs baseline: 1.2764x; 1.2764x over previous
#include <cuda_runtime.h>

#define NB   128
#define NBP  129          // padded row stride: bank = (i + j) % 32
#define RAD  4
#define W    (2*RAD+1)    // 9

__device__ float g_hist[NB * NB];   // zero-initialized at module load; re-zeroed by normalize

__global__ void accum_kernel(const float* __restrict__ x,
                             const float* __restrict__ ex,
                             const float* __restrict__ ey,
                             int n) {
    extern __shared__ float sh[];   // NB * NBP floats
    for (int i = threadIdx.x; i < NB * NBP; i += blockDim.x) sh[i] = 0.0f;
    __syncthreads();

    const float bwx = ex[1] - ex[0];
    const float bwy = ey[1] - ey[0];
    const float inv_bwx = 1.0f / bwx;
    const float inv_bwy = 1.0f / bwy;
    const float c0x = 0.5f * (ex[0] + ex[1]);
    const float c0y = 0.5f * (ey[0] + ey[1]);
    const float EINV = 0.36787944117144233f;   // e^-1

    const int stride = gridDim.x * blockDim.x;
    for (int p = blockIdx.x * blockDim.x + threadIdx.x; p < n; p += stride) {
        // x is [n,6]; dims 0,1 are adjacent and 8B-aligned (24B row stride)
        float2 pt = __ldg((const float2*)(x + p * 6));
        float ux = (pt.x - c0x) * inv_bwx;    // position in bin units
        float uy = (pt.y - c0y) * inv_bwy;
        int ix0 = __float2int_rn(ux);
        int iy0 = __float2int_rn(uy);

        if (ix0 >= RAD && ix0 <= NB - 1 - RAD && iy0 >= RAD && iy0 <= NB - 1 - RAD) {
            // ---- fast interior path: full 9x9 window, no clamps ----
            const int ilo = ix0 - RAD, jlo = iy0 - RAD;
            float kv[W];
            {
                float z = uy - (float)jlo;
                float g = __expf(-0.5f * z * z);
                float r = __expf(z - 0.5f);
                #pragma unroll
                for (int jj = 0; jj < W; ++jj) { kv[jj] = g; g *= r; r *= EINV; }
            }
            float z = ux - (float)ilo;
            float g = __expf(-0.5f * z * z);
            float r = __expf(z - 0.5f);
            float* base = &sh[ilo * NBP + jlo];
            #pragma unroll
            for (int ii = 0; ii < W; ++ii) {
                float* row = base + ii * NBP;
                #pragma unroll
                for (int jj = 0; jj < W; ++jj) atomicAdd(&row[jj], g * kv[jj]);
                g *= r;
                r *= EINV;
            }
        } else {
            // ---- rare edge path (P ~ 3.6e-4): clamped window ----
            int ilo = max(0, ix0 - RAD), ihi = min(NB - 1, ix0 + RAD);
            int jlo = max(0, iy0 - RAD), jhi = min(NB - 1, iy0 + RAD);
            if (ilo > ihi || jlo > jhi) continue;
            int my = jhi - jlo + 1;
            float kv[W];
            {
                float z = uy - (float)jlo;
                float g = __expf(-0.5f * z * z);
                float r = __expf(z - 0.5f);
                #pragma unroll
                for (int jj = 0; jj < W; ++jj) { kv[jj] = g; g *= r; r *= EINV; }
            }
            float z = ux - (float)ilo;
            float g = __expf(-0.5f * z * z);
            float r = __expf(z - 0.5f);
            for (int i = ilo; i <= ihi; ++i) {
                float* row = &sh[i * NBP + jlo];
                #pragma unroll
                for (int jj = 0; jj < W; ++jj)
                    if (jj < my) atomicAdd(&row[jj], g * kv[jj]);
                g *= r;
                r *= EINV;
            }
        }
    }

    __syncthreads();
    // flush block-private hist to global
    for (int i = threadIdx.x; i < NB * NB; i += blockDim.x) {
        float v = sh[(i >> 7) * NBP + (i & (NB - 1))];
        if (v != 0.0f) atomicAdd(&g_hist[i], v);
    }
}

__global__ void normalize_kernel(float* __restrict__ out,
                                 const float* __restrict__ ex,
                                 const float* __restrict__ ey) {
    __shared__ float red[1024];
    float s = 0.0f;
    for (int i = threadIdx.x; i < NB * NB; i += 1024) s += g_hist[i];
    red[threadIdx.x] = s;
    __syncthreads();
    for (int off = 512; off > 0; off >>= 1) {
        if (threadIdx.x < off) red[threadIdx.x] += red[threadIdx.x + off];
        __syncthreads();
    }
    float bwx = ex[1] - ex[0];
    float bwy = ey[1] - ey[0];
    float scale = 1.0f / (red[0] * bwx * bwy);
    // write output and re-zero g_hist so the next graph replay starts clean
    for (int i = threadIdx.x; i < NB * NB; i += 1024) {
        out[i] = g_hist[i] * scale;
        g_hist[i] = 0.0f;
    }
}

extern "C" void kernel_launch(void* const* d_in, const int* in_sizes, int n_in,
                              void* d_out, int out_size) {
    const float* x  = (const float*)d_in[0];
    const float* ex = (const float*)d_in[1];
    const float* ey = (const float*)d_in[2];
    int n = in_sizes[0] / 6;

    const int SMEM = NB * NBP * (int)sizeof(float);   // 66048 B
    cudaFuncSetAttribute(accum_kernel, cudaFuncAttributeMaxDynamicSharedMemorySize, SMEM);

    // 3 CTAs/SM * 148 SMs = 444 persistent blocks
    accum_kernel<<<444, 256, SMEM>>>(x, ex, ey, n);
    normalize_kernel<<<1, 1024>>>((float*)d_out, ex, ey);
}

// round 3
// speedup vs baseline: 1.8853x; 1.4771x over previous
#include <cuda_runtime.h>

#define NB   128
#define NBP  129          // padded row stride: bank = (i*129 + j) % 32 mixes both indices
#define RAD  3
#define W    (2*RAD+1)    // 7
#define NBLK 148
#define NTHR 768

__device__ float g_hist[NB * NB];   // zeroed at load; re-zeroed by normalize each replay
__device__ float g_sum;             // ditto

__global__ void __launch_bounds__(NTHR, 1)
accum_kernel(const float* __restrict__ x,
             const float* __restrict__ ex,
             const float* __restrict__ ey,
             int n) {
    extern __shared__ float sh[];   // NB * NBP floats
    __shared__ float blk_sum;
    for (int i = threadIdx.x; i < NB * NBP; i += NTHR) sh[i] = 0.0f;
    if (threadIdx.x == 0) blk_sum = 0.0f;
    __syncthreads();

    const float bwx = ex[1] - ex[0];
    const float bwy = ey[1] - ey[0];
    const float inv_bwx = 1.0f / bwx;
    const float inv_bwy = 1.0f / bwy;
    const float c0x = 0.5f * (ex[0] + ex[1]);
    const float c0y = 0.5f * (ey[0] + ey[1]);
    const float EINV = 0.36787944117144233f;   // e^-1

    const int stride = gridDim.x * NTHR;
    for (int p = blockIdx.x * NTHR + threadIdx.x; p < n; p += stride) {
        // x is [n,6]; dims 0,1 adjacent, 24B row stride keeps 8B alignment
        float2 pt = __ldg((const float2*)(x + p * 6));
        float ux = (pt.x - c0x) * inv_bwx;    // position in bin-center units
        float uy = (pt.y - c0y) * inv_bwy;
        int ix0 = __float2int_rn(ux);
        int iy0 = __float2int_rn(uy);

        if (ix0 >= RAD && ix0 <= NB - 1 - RAD && iy0 >= RAD && iy0 <= NB - 1 - RAD) {
            // ---- fast interior path: full 7x7 window, no clamps ----
            const int ilo = ix0 - RAD, jlo = iy0 - RAD;
            float kv[W];
            {
                float z = uy - (float)jlo;
                float g = __expf(-0.5f * z * z);
                float r = __expf(z - 0.5f);
                #pragma unroll
                for (int jj = 0; jj < W; ++jj) { kv[jj] = g; g *= r; r *= EINV; }
            }
            float z = ux - (float)ilo;
            float g = __expf(-0.5f * z * z);
            float r = __expf(z - 0.5f);
            float* base = &sh[ilo * NBP + jlo];
            #pragma unroll
            for (int ii = 0; ii < W; ++ii) {
                float* row = base + ii * NBP;
                #pragma unroll
                for (int jj = 0; jj < W; ++jj) atomicAdd(&row[jj], g * kv[jj]);
                g *= r;
                r *= EINV;
            }
        } else {
            // ---- rare edge path: clamped window ----
            int ilo = max(0, ix0 - RAD), ihi = min(NB - 1, ix0 + RAD);
            int jlo = max(0, iy0 - RAD), jhi = min(NB - 1, iy0 + RAD);
            if (ilo > ihi || jlo > jhi) continue;
            int my = jhi - jlo + 1;
            float kv[W];
            {
                float z = uy - (float)jlo;
                float g = __expf(-0.5f * z * z);
                float r = __expf(z - 0.5f);
                #pragma unroll
                for (int jj = 0; jj < W; ++jj) { kv[jj] = g; g *= r; r *= EINV; }
            }
            float z = ux - (float)ilo;
            float g = __expf(-0.5f * z * z);
            float r = __expf(z - 0.5f);
            for (int i = ilo; i <= ihi; ++i) {
                float* row = &sh[i * NBP + jlo];
                #pragma unroll
                for (int jj = 0; jj < W; ++jj)
                    if (jj < my) atomicAdd(&row[jj], g * kv[jj]);
                g *= r;
                r *= EINV;
            }
        }
    }

    __syncthreads();
    // flush block-private hist to global; accumulate block total for normalization
    float my_sum = 0.0f;
    for (int i = threadIdx.x; i < NB * NB; i += NTHR) {
        float v = sh[(i >> 7) * NBP + (i & (NB - 1))];
        my_sum += v;
        if (v != 0.0f) atomicAdd(&g_hist[i], v);
    }
    // warp reduce then one shared atomic per warp
    #pragma unroll
    for (int off = 16; off > 0; off >>= 1)
        my_sum += __shfl_down_sync(0xffffffffu, my_sum, off);
    if ((threadIdx.x & 31) == 0) atomicAdd(&blk_sum, my_sum);
    __syncthreads();
    if (threadIdx.x == 0) atomicAdd(&g_sum, blk_sum);
}

__global__ void normalize_kernel(float* __restrict__ out,
                                 const float* __restrict__ ex,
                                 const float* __restrict__ ey) {
    const float bwx = ex[1] - ex[0];
    const float bwy = ey[1] - ey[0];
    const float scale = 1.0f / (g_sum * bwx * bwy);   // every thread reads before any write
    __syncthreads();
    for (int i = threadIdx.x; i < NB * NB; i += 1024) {
        out[i] = g_hist[i] * scale;
        g_hist[i] = 0.0f;       // reset for next graph replay
    }
    if (threadIdx.x == 0) g_sum = 0.0f;
}

extern "C" void kernel_launch(void* const* d_in, const int* in_sizes, int n_in,
                              void* d_out, int out_size) {
    const float* x  = (const float*)d_in[0];
    const float* ex = (const float*)d_in[1];
    const float* ey = (const float*)d_in[2];
    int n = in_sizes[0] / 6;

    const int SMEM = NB * NBP * (int)sizeof(float);   // 66048 B
    cudaFuncSetAttribute(accum_kernel, cudaFuncAttributeMaxDynamicSharedMemorySize, SMEM);

    accum_kernel<<<NBLK, NTHR, SMEM>>>(x, ex, ey, n);
    normalize_kernel<<<1, 1024>>>((float*)d_out, ex, ey);
}

// round 4
// speedup vs baseline: 2.3336x; 1.2378x over previous
#include <cuda_runtime.h>

#define NB   128
#define NBP  129          // padded row stride: bank = (i*129 + j) % 32 mixes both indices
#define RAD  3
#define W    (2*RAD+1)    // 7
#define NBLK 296          // 2 CTAs/SM
#define NTHR 768

__device__ float g_hist[NB * NB];   // zeroed at load; re-zeroed by normalize each replay
__device__ float g_sum;
__device__ float g_scale;

// elliptical window: keep di*di+dj*dj <= 10  -> rows {3,5,7,7,7,5,3} = 37 cells
__device__ __constant__ int JLO[W] = {2, 1, 0, 0, 0, 1, 2};
__device__ __constant__ int JHI[W] = {4, 5, 6, 6, 6, 5, 4};

__global__ void __launch_bounds__(NTHR, 2)
accum_kernel(const float* __restrict__ x,
             const float* __restrict__ ex,
             const float* __restrict__ ey,
             int n) {
    extern __shared__ float sh[];   // NB * NBP floats
    __shared__ float blk_sum;
    for (int i = threadIdx.x; i < NB * NBP; i += NTHR) sh[i] = 0.0f;
    if (threadIdx.x == 0) blk_sum = 0.0f;
    __syncthreads();

    const float bwx = ex[1] - ex[0];
    const float bwy = ey[1] - ey[0];
    const float inv_bwx = 1.0f / bwx;
    const float inv_bwy = 1.0f / bwy;
    const float c0x = 0.5f * (ex[0] + ex[1]);
    const float c0y = 0.5f * (ey[0] + ey[1]);
    const float EINV = 0.36787944117144233f;   // e^-1

    const int stride = gridDim.x * NTHR;
    for (int p = blockIdx.x * NTHR + threadIdx.x; p < n; p += stride) {
        // x is [n,6]; dims 0,1 adjacent, 24B row stride keeps 8B alignment
        float2 pt = __ldg((const float2*)(x + p * 6));
        float ux = (pt.x - c0x) * inv_bwx;    // position in bin-center units
        float uy = (pt.y - c0y) * inv_bwy;
        int ix0 = __float2int_rn(ux);
        int iy0 = __float2int_rn(uy);

        if (ix0 >= RAD && ix0 <= NB - 1 - RAD && iy0 >= RAD && iy0 <= NB - 1 - RAD) {
            // ---- fast interior path: elliptical window, no clamps ----
            const int ilo = ix0 - RAD, jlo = iy0 - RAD;
            float kv[W];
            {
                float z = uy - (float)jlo;
                float g = __expf(-0.5f * z * z);
                float r = __expf(z - 0.5f);
                #pragma unroll
                for (int jj = 0; jj < W; ++jj) { kv[jj] = g; g *= r; r *= EINV; }
            }
            float z = ux - (float)ilo;
            float g = __expf(-0.5f * z * z);
            float r = __expf(z - 0.5f);
            float* base = &sh[ilo * NBP + jlo];
            #pragma unroll
            for (int ii = 0; ii < W; ++ii) {
                float* row = base + ii * NBP;
                #pragma unroll
                for (int jj = 0; jj < W; ++jj) {
                    if (jj >= JLO[ii] && jj <= JHI[ii])   // static, resolved at unroll
                        atomicAdd(&row[jj], g * kv[jj]);
                }
                g *= r;
                r *= EINV;
            }
        } else {
            // ---- rare edge path: clamped rectangular window ----
            int ilo = max(0, ix0 - RAD), ihi = min(NB - 1, ix0 + RAD);
            int jlo = max(0, iy0 - RAD), jhi = min(NB - 1, iy0 + RAD);
            if (ilo > ihi || jlo > jhi) continue;
            int my = jhi - jlo + 1;
            float kv[W];
            {
                float z = uy - (float)jlo;
                float g = __expf(-0.5f * z * z);
                float r = __expf(z - 0.5f);
                #pragma unroll
                for (int jj = 0; jj < W; ++jj) { kv[jj] = g; g *= r; r *= EINV; }
            }
            float z = ux - (float)ilo;
            float g = __expf(-0.5f * z * z);
            float r = __expf(z - 0.5f);
            for (int i = ilo; i <= ihi; ++i) {
                float* row = &sh[i * NBP + jlo];
                #pragma unroll
                for (int jj = 0; jj < W; ++jj)
                    if (jj < my) atomicAdd(&row[jj], g * kv[jj]);
                g *= r;
                r *= EINV;
            }
        }
    }

    __syncthreads();
    // flush block-private hist to global; accumulate block total for normalization
    float my_sum = 0.0f;
    for (int i = threadIdx.x; i < NB * NB; i += NTHR) {
        float v = sh[(i >> 7) * NBP + (i & (NB - 1))];
        my_sum += v;
        if (v != 0.0f) atomicAdd(&g_hist[i], v);
    }
    #pragma unroll
    for (int off = 16; off > 0; off >>= 1)
        my_sum += __shfl_down_sync(0xffffffffu, my_sum, off);
    if ((threadIdx.x & 31) == 0) atomicAdd(&blk_sum, my_sum);
    __syncthreads();
    if (threadIdx.x == 0) atomicAdd(&g_sum, blk_sum);
}

__global__ void scale_kernel(const float* __restrict__ ex,
                             const float* __restrict__ ey) {
    float bwx = ex[1] - ex[0];
    float bwy = ey[1] - ey[0];
    g_scale = 1.0f / (g_sum * bwx * bwy);
    g_sum = 0.0f;   // reset for next graph replay
}

__global__ void normalize_kernel(float* __restrict__ out) {
    int i = blockIdx.x * blockDim.x + threadIdx.x;   // 64 CTAs x 256 = 16384 = NB*NB
    out[i] = g_hist[i] * g_scale;
    g_hist[i] = 0.0f;   // reset for next graph replay
}

extern "C" void kernel_launch(void* const* d_in, const int* in_sizes, int n_in,
                              void* d_out, int out_size) {
    const float* x  = (const float*)d_in[0];
    const float* ex = (const float*)d_in[1];
    const float* ey = (const float*)d_in[2];
    int n = in_sizes[0] / 6;

    const int SMEM = NB * NBP * (int)sizeof(float);   // 66048 B
    cudaFuncSetAttribute(accum_kernel, cudaFuncAttributeMaxDynamicSharedMemorySize, SMEM);

    accum_kernel<<<NBLK, NTHR, SMEM>>>(x, ex, ey, n);
    scale_kernel<<<1, 1>>>(ex, ey);
    normalize_kernel<<<(NB * NB) / 256, 256>>>((float*)d_out);
}